// round 2
// baseline (speedup 1.0000x reference)
#include <cuda_runtime.h>
#include <cuda_bf16.h>
#include <cstdint>

// Problem constants
#define BATCH 8
#define SEQ   2048
#define EMB   126
#define NH    6
#define HD    21
#define PD    24      // padded head dim (for f32x2 / alignment)
#define PD2   12      // packed pairs per row
#define QTILE 256     // queries per CTA (2 per thread, 128 threads)
#define BK    16      // key tile
#define ROWS  (BATCH*SEQ)   // 16384

// Scratch (no allocations allowed; use device globals)
__device__ float g_q[BATCH*NH*SEQ*HD];
__device__ float g_k[BATCH*NH*SEQ*HD];
__device__ float g_v[BATCH*NH*SEQ*HD];
__device__ float g_att[ROWS*EMB];

typedef unsigned long long u64;

__device__ __forceinline__ u64 fma2(u64 a, u64 b, u64 c) {
    u64 d; asm("fma.rn.f32x2 %0, %1, %2, %3;" : "=l"(d) : "l"(a), "l"(b), "l"(c)); return d;
}
__device__ __forceinline__ u64 mul2(u64 a, u64 b) {
    u64 d; asm("mul.rn.f32x2 %0, %1, %2;" : "=l"(d) : "l"(a), "l"(b)); return d;
}
__device__ __forceinline__ u64 pack2(float lo, float hi) {
    u64 d; asm("mov.b64 %0, {%1, %2};" : "=l"(d) : "f"(lo), "f"(hi)); return d;
}
__device__ __forceinline__ float2 unpack2(u64 v) {
    float2 r; asm("mov.b64 {%0, %1}, %2;" : "=f"(r.x), "=f"(r.y) : "l"(v)); return r;
}

// ---------------------------------------------------------------------------
// Kernel 1: QKV projection. C[16384,378] = X[16384,126] @ Wattn[126,378],
// scattered into g_q/g_k/g_v with [B,H,T,HD] layout.
// ---------------------------------------------------------------------------
__global__ __launch_bounds__(256) void qkv_gemm_kernel(const float* __restrict__ X,
                                                       const float* __restrict__ W) {
    __shared__ float As[64][43];
    __shared__ float Ws[42][65];
    const int bx = blockIdx.x;          // col tile (0..5), 64 cols each
    const int by = blockIdx.y;          // row tile (0..255)
    const int tid = threadIdx.x;
    const int tx = tid & 15, ty = tid >> 4;
    const int row0 = by * 64, col0 = bx * 64;

    float acc[4][4];
#pragma unroll
    for (int i = 0; i < 4; i++)
#pragma unroll
        for (int j = 0; j < 4; j++) acc[i][j] = 0.f;

    for (int k0 = 0; k0 < 126; k0 += 42) {
        for (int idx = tid; idx < 64 * 42; idx += 256) {
            int r = idx / 42, c = idx % 42;
            As[r][c] = X[(size_t)(row0 + r) * 126 + (k0 + c)];
        }
        for (int idx = tid; idx < 42 * 64; idx += 256) {
            int r = idx >> 6, c = idx & 63;
            int gc = col0 + c;
            Ws[r][c] = (gc < 378) ? W[(size_t)(k0 + r) * 378 + gc] : 0.f;
        }
        __syncthreads();
#pragma unroll
        for (int kk = 0; kk < 42; kk++) {
            float a[4], b[4];
#pragma unroll
            for (int i = 0; i < 4; i++) a[i] = As[ty * 4 + i][kk];
#pragma unroll
            for (int j = 0; j < 4; j++) b[j] = Ws[kk][tx * 4 + j];
#pragma unroll
            for (int i = 0; i < 4; i++)
#pragma unroll
                for (int j = 0; j < 4; j++) acc[i][j] = fmaf(a[i], b[j], acc[i][j]);
        }
        __syncthreads();
    }
    // Scatter into q/k/v [B,H,T,HD]
#pragma unroll
    for (int i = 0; i < 4; i++) {
        int r = row0 + ty * 4 + i;          // r = b*SEQ + t
        int b_ = r >> 11, t_ = r & 2047;
#pragma unroll
        for (int j = 0; j < 4; j++) {
            int c = col0 + tx * 4 + j;
            if (c >= 378) continue;
            int which = c / 126, cc = c % 126;
            int h = cc / HD, d = cc % HD;
            float* dst = (which == 0) ? g_q : ((which == 1) ? g_k : g_v);
            dst[(((size_t)(b_ * NH + h)) * SEQ + t_) * HD + d] = acc[i][j];
        }
    }
}

// ---------------------------------------------------------------------------
// Kernel 2: Causal flash attention, fp32 packed f32x2, 2 queries per thread,
// LDS.128 shared reads. Grid: (SEQ/QTILE, NH, BATCH); 128 threads.
// Output to g_att as [B,T,C] (c = h*HD + d) for the proj GEMM.
// ---------------------------------------------------------------------------
__global__ __launch_bounds__(128) void attn_kernel() {
    const int blkq = (gridDim.x - 1) - blockIdx.x;   // heavy blocks first
    const int h = blockIdx.y;
    const int b = blockIdx.z;
    const int tid = threadIdx.x;
    const int base = blkq * QTILE;
    const int qi0 = base + 2 * tid;
    const int qi1 = qi0 + 1;

    __shared__ __align__(16) u64 Ks[BK][PD2];
    __shared__ __align__(16) u64 Vs[BK][PD2];

    const size_t head_base = ((size_t)(b * NH + h)) * SEQ * HD;
    const float* qp0 = g_q + head_base + (size_t)qi0 * HD;
    const float* qp1 = g_q + head_base + (size_t)qi1 * HD;

    u64 qa[PD2], qb[PD2], acc0[PD2], acc1[PD2];
#pragma unroll
    for (int i = 0; i < PD2; i++) {
        float a0 = (2 * i     < HD) ? qp0[2 * i]     : 0.f;
        float a1 = (2 * i + 1 < HD) ? qp0[2 * i + 1] : 0.f;
        float b0 = (2 * i     < HD) ? qp1[2 * i]     : 0.f;
        float b1 = (2 * i + 1 < HD) ? qp1[2 * i + 1] : 0.f;
        qa[i] = pack2(a0, a1);
        qb[i] = pack2(b0, b1);
        acc0[i] = 0ull; acc1[i] = 0ull;
    }

    float m0 = -1e30f, l0 = 0.f, m1 = -1e30f, l1 = 0.f;
    const float scale = 0.21821789f;     // 1/sqrt(21)

    const int ntiles = (base + QTILE) / BK;
    for (int kt = 0; kt < ntiles; kt++) {
        const int kstart = kt * BK;
        __syncthreads();
        // Cooperative tile load, zero-padded hd 21 -> 24
        for (int idx = tid; idx < BK * PD; idx += 128) {
            int j = idx / PD, d = idx - j * PD;
            size_t g = head_base + (size_t)(kstart + j) * HD + d;
            float kv = (d < HD) ? g_k[g] : 0.f;
            float vv = (d < HD) ? g_v[g] : 0.f;
            ((float*)Ks)[idx] = kv;
            ((float*)Vs)[idx] = vv;
        }
        __syncthreads();
        if (kstart > qi1) continue;       // fully masked tile for both queries

        float s0[BK], s1[BK];
#pragma unroll
        for (int j = 0; j < BK; j++) {
            u64 d0 = 0ull, d1 = 0ull;
#pragma unroll
            for (int i2 = 0; i2 < PD2 / 2; i2++) {
                ulonglong2 kk = *(const ulonglong2*)&Ks[j][2 * i2];
                d0 = fma2(qa[2 * i2],     kk.x, d0);
                d0 = fma2(qa[2 * i2 + 1], kk.y, d0);
                d1 = fma2(qb[2 * i2],     kk.x, d1);
                d1 = fma2(qb[2 * i2 + 1], kk.y, d1);
            }
            float2 e0 = unpack2(d0), e1 = unpack2(d1);
            s0[j] = (e0.x + e0.y) * scale;
            s1[j] = (e1.x + e1.y) * scale;
        }
        float mt0 = -1e30f, mt1 = -1e30f;
#pragma unroll
        for (int j = 0; j < BK; j++) {
            if (kstart + j > qi0) s0[j] = -1e30f;
            if (kstart + j > qi1) s1[j] = -1e30f;
            mt0 = fmaxf(mt0, s0[j]);
            mt1 = fmaxf(mt1, s1[j]);
        }
        const float mn0 = fmaxf(m0, mt0);
        const float mn1 = fmaxf(m1, mt1);
        const float al0 = __expf(m0 - mn0);
        const float al1 = __expf(m1 - mn1);
        l0 *= al0; l1 *= al1;
        const u64 a02 = pack2(al0, al0);
        const u64 a12 = pack2(al1, al1);
#pragma unroll
        for (int i = 0; i < PD2; i++) { acc0[i] = mul2(acc0[i], a02); acc1[i] = mul2(acc1[i], a12); }
#pragma unroll
        for (int j = 0; j < BK; j++) {
            float p0 = __expf(s0[j] - mn0);   // masked lanes -> 0
            float p1 = __expf(s1[j] - mn1);
            l0 += p0; l1 += p1;
            const u64 p02 = pack2(p0, p0);
            const u64 p12 = pack2(p1, p1);
#pragma unroll
            for (int i2 = 0; i2 < PD2 / 2; i2++) {
                ulonglong2 vv = *(const ulonglong2*)&Vs[j][2 * i2];
                acc0[2 * i2]     = fma2(p02, vv.x, acc0[2 * i2]);
                acc0[2 * i2 + 1] = fma2(p02, vv.y, acc0[2 * i2 + 1]);
                acc1[2 * i2]     = fma2(p12, vv.x, acc1[2 * i2]);
                acc1[2 * i2 + 1] = fma2(p12, vv.y, acc1[2 * i2 + 1]);
            }
        }
        m0 = mn0; m1 = mn1;
    }

    const float inv0 = 1.f / l0;
    const float inv1 = 1.f / l1;
    float* op0 = g_att + ((size_t)(b * SEQ + qi0)) * EMB + h * HD;
    float* op1 = g_att + ((size_t)(b * SEQ + qi1)) * EMB + h * HD;
#pragma unroll
    for (int i = 0; i < PD2; i++) {
        float2 v0 = unpack2(acc0[i]);
        float2 v1 = unpack2(acc1[i]);
        int d = 2 * i;
        if (d < HD)     { op0[d]     = v0.x * inv0; op1[d]     = v1.x * inv1; }
        if (d + 1 < HD) { op0[d + 1] = v0.y * inv0; op1[d + 1] = v1.y * inv1; }
    }
}

// ---------------------------------------------------------------------------
// Kernel 3: output projection. Y[16384,126] = g_att[16384,126] @ Wproj[126,126]
// ---------------------------------------------------------------------------
__global__ __launch_bounds__(256) void proj_gemm_kernel(const float* __restrict__ W,
                                                        float* __restrict__ Y) {
    __shared__ float As[64][43];
    __shared__ float Ws[42][65];
    const int bx = blockIdx.x;          // col tile (0..1)
    const int by = blockIdx.y;          // row tile (0..255)
    const int tid = threadIdx.x;
    const int tx = tid & 15, ty = tid >> 4;
    const int row0 = by * 64, col0 = bx * 64;

    float acc[4][4];
#pragma unroll
    for (int i = 0; i < 4; i++)
#pragma unroll
        for (int j = 0; j < 4; j++) acc[i][j] = 0.f;

    for (int k0 = 0; k0 < 126; k0 += 42) {
        for (int idx = tid; idx < 64 * 42; idx += 256) {
            int r = idx / 42, c = idx % 42;
            As[r][c] = g_att[(size_t)(row0 + r) * 126 + (k0 + c)];
        }
        for (int idx = tid; idx < 42 * 64; idx += 256) {
            int r = idx >> 6, c = idx & 63;
            int gc = col0 + c;
            Ws[r][c] = (gc < 126) ? W[(size_t)(k0 + r) * 126 + gc] : 0.f;
        }
        __syncthreads();
#pragma unroll
        for (int kk = 0; kk < 42; kk++) {
            float a[4], b[4];
#pragma unroll
            for (int i = 0; i < 4; i++) a[i] = As[ty * 4 + i][kk];
#pragma unroll
            for (int j = 0; j < 4; j++) b[j] = Ws[kk][tx * 4 + j];
#pragma unroll
            for (int i = 0; i < 4; i++)
#pragma unroll
                for (int j = 0; j < 4; j++) acc[i][j] = fmaf(a[i], b[j], acc[i][j]);
        }
        __syncthreads();
    }
#pragma unroll
    for (int i = 0; i < 4; i++) {
        int r = row0 + ty * 4 + i;
#pragma unroll
        for (int j = 0; j < 4; j++) {
            int c = col0 + tx * 4 + j;
            if (c < 126) Y[(size_t)r * 126 + c] = acc[i][j];
        }
    }
}

// ---------------------------------------------------------------------------
extern "C" void kernel_launch(void* const* d_in, const int* in_sizes, int n_in,
                              void* d_out, int out_size) {
    const float* x      = (const float*)d_in[0];   // [8,2048,126]
    const float* w_attn = (const float*)d_in[1];   // [126,378]
    const float* w_proj = (const float*)d_in[2];   // [126,126]
    float* y = (float*)d_out;                      // [8,2048,126]

    (void)in_sizes; (void)n_in; (void)out_size;

    // 1) QKV projection + head scatter
    {
        dim3 grid(6, ROWS / 64);
        qkv_gemm_kernel<<<grid, 256>>>(x, w_attn);
    }
    // 2) Causal attention
    {
        dim3 grid(SEQ / QTILE, NH, BATCH);
        attn_kernel<<<grid, 128>>>();
    }
    // 3) Output projection
    {
        dim3 grid(2, ROWS / 64);
        proj_gemm_kernel<<<grid, 256>>>(w_proj, y);
    }
}